// round 17
// baseline (speedup 1.0000x reference)
#include <cuda_runtime.h>
#include <cuda_bf16.h>
#include <cstdint>

#define S_LEN  1024
#define D_DIM  1024
#define N_ST   64
#define B_SZ   16
#define M_TOT  (B_SZ * S_LEN)
#define KSPLIT 4

typedef unsigned long long u64;

// ---------------------------------------------------------------------------
// Scratch (device globals; no runtime allocation allowed)
// ---------------------------------------------------------------------------
__device__ float g_sgA[D_DIM * N_ST];
__device__ float g_sgB[N_ST * D_DIM];
__device__ float g_sgC[D_DIM * N_ST];
__device__ float g_sgG[D_DIM];
__device__ float g_sumC[D_DIM];
__device__ float g_part[(size_t)KSPLIT * M_TOT * N_ST];   // split-K partials (16 MB)
__device__ float g_bproj[M_TOT * N_ST];
__device__ float g_minb[M_TOT];
__device__ float g_yraw[(size_t)M_TOT * D_DIM];

__device__ __forceinline__ float sigf(float v) { return 1.0f / (1.0f + expf(-v)); }

// ---- packed f32x2 helpers (Blackwell sm_103a; PTX-portable, no tcgen05) ----
__device__ __forceinline__ u64 pk2(float lo, float hi) {
    u64 r; asm("mov.b64 %0, {%1, %2};" : "=l"(r) : "f"(lo), "f"(hi)); return r;
}
__device__ __forceinline__ u64 fma2_(u64 a, u64 b, u64 c) {
    u64 d; asm("fma.rn.f32x2 %0, %1, %2, %3;" : "=l"(d) : "l"(a), "l"(b), "l"(c)); return d;
}

// ---------------------------------------------------------------------------
// K1: precompute sigmoids + sumC
// ---------------------------------------------------------------------------
__global__ void precompute_kernel(const float* __restrict__ A,
                                  const float* __restrict__ WB,
                                  const float* __restrict__ WC,
                                  const float* __restrict__ gamma) {
    int i = blockIdx.x * blockDim.x + threadIdx.x;
    if (i < D_DIM * N_ST) {
        g_sgA[i] = sigf(A[i]);
        g_sgB[i] = sigf(WB[i]);
        g_sgC[i] = sigf(WC[i]);
    }
    if (i < D_DIM) {
        g_sgG[i] = sigf(gamma[i]);
        const float* c = WC + (size_t)i * N_ST;
        float s = 0.0f;
        #pragma unroll
        for (int q = 0; q < N_ST; q++) s += sigf(c[q]);
        g_sumC[i] = s;
    }
}

// ---------------------------------------------------------------------------
// K2: split-K GEMM partials. grid = 128 m-tiles x 4 k-splits = 512 CTAs.
// x tile stored PRE-DUPLICATED in smem (u64 = (x,x)) so the inner loop has
// zero pack MOVs: per thread per kk = 6 LDS.128 + 32 fma2.
// ---------------------------------------------------------------------------
__global__ __launch_bounds__(128, 4) void bproj_gemm(const float* __restrict__ X) {
    __shared__ __align__(16) u64   xs2[2][16][128];  // 32 KB (duplicated x)
    __shared__ __align__(16) float bs[2][16][64];    // 8 KB

    const int mt = blockIdx.x >> 2;
    const int ks = blockIdx.x & 3;
    const int m0 = mt * 128;
    const int kb = ks * 256;

    const int tid  = threadIdx.x;
    const int trow = tid >> 3;      // 0..15 -> rows trow*8 .. +7
    const int tcol = tid & 7;       // 0..7  -> cols tcol*8 .. +7 (4 n-pairs)

    u64 acc[8][4];                  // [m][n-pair]
    #pragma unroll
    for (int i = 0; i < 8; i++)
        #pragma unroll
        for (int j = 0; j < 4; j++) acc[i][j] = 0ull;

    const int bn = tid & 63, bkq = tid >> 6;   // b: 2 float4/thread (8 k)

    // prologue: stage 0
    {
        const float4* xg = (const float4*)(X + (size_t)(m0 + tid) * D_DIM + kb);
        #pragma unroll
        for (int j = 0; j < 4; j++) {
            float4 v = xg[j];
            xs2[0][j * 4 + 0][tid] = pk2(v.x, v.x);
            xs2[0][j * 4 + 1][tid] = pk2(v.y, v.y);
            xs2[0][j * 4 + 2][tid] = pk2(v.z, v.z);
            xs2[0][j * 4 + 3][tid] = pk2(v.w, v.w);
        }
        const float4* bg = (const float4*)(g_sgB + (size_t)bn * D_DIM + kb + bkq * 8);
        #pragma unroll
        for (int j = 0; j < 2; j++) {
            float4 v = bg[j];
            const int k = bkq * 8 + j * 4;
            bs[0][k + 0][bn] = v.x; bs[0][k + 1][bn] = v.y;
            bs[0][k + 2][bn] = v.z; bs[0][k + 3][bn] = v.w;
        }
    }
    __syncthreads();

    for (int it = 0; it < 16; it++) {
        const int cur = it & 1, nxt = cur ^ 1;
        float4 xr[4], br[2];
        if (it < 15) {
            const int k0 = kb + (it + 1) * 16;
            const float4* xg = (const float4*)(X + (size_t)(m0 + tid) * D_DIM + k0);
            #pragma unroll
            for (int j = 0; j < 4; j++) xr[j] = xg[j];
            const float4* bg = (const float4*)(g_sgB + (size_t)bn * D_DIM + k0 + bkq * 8);
            br[0] = bg[0];
            br[1] = bg[1];
        }

        #pragma unroll
        for (int kk = 0; kk < 16; kk++) {
            const ulonglong2* xrow = (const ulonglong2*)&xs2[cur][kk][trow * 8];
            ulonglong2 xa = xrow[0], xb = xrow[1], xc = xrow[2], xd4 = xrow[3];
            const u64 xd[8] = {xa.x, xa.y, xb.x, xb.y, xc.x, xc.y, xd4.x, xd4.y};
            const ulonglong2* brow = (const ulonglong2*)&bs[cur][kk][0];
            ulonglong2 b01 = brow[tcol * 2 + 0];
            ulonglong2 b23 = brow[tcol * 2 + 1];
            #pragma unroll
            for (int i = 0; i < 8; i++) {
                acc[i][0] = fma2_(b01.x, xd[i], acc[i][0]);
                acc[i][1] = fma2_(b01.y, xd[i], acc[i][1]);
                acc[i][2] = fma2_(b23.x, xd[i], acc[i][2]);
                acc[i][3] = fma2_(b23.y, xd[i], acc[i][3]);
            }
        }

        if (it < 15) {
            #pragma unroll
            for (int j = 0; j < 4; j++) {
                xs2[nxt][j * 4 + 0][tid] = pk2(xr[j].x, xr[j].x);
                xs2[nxt][j * 4 + 1][tid] = pk2(xr[j].y, xr[j].y);
                xs2[nxt][j * 4 + 2][tid] = pk2(xr[j].z, xr[j].z);
                xs2[nxt][j * 4 + 3][tid] = pk2(xr[j].w, xr[j].w);
            }
            #pragma unroll
            for (int j = 0; j < 2; j++) {
                const int k = bkq * 8 + j * 4;
                bs[nxt][k + 0][bn] = br[j].x;
                bs[nxt][k + 1][bn] = br[j].y;
                bs[nxt][k + 2][bn] = br[j].z;
                bs[nxt][k + 3][bn] = br[j].w;
            }
        }
        __syncthreads();
    }

    // writeback partials (acc pairs are along n, rows independent)
    float* base = g_part + ((size_t)ks * M_TOT + m0) * N_ST;
    #pragma unroll
    for (int i = 0; i < 8; i++) {
        ulonglong2* p = (ulonglong2*)(base + (size_t)(trow * 8 + i) * N_ST + tcol * 8);
        p[0] = make_ulonglong2(acc[i][0], acc[i][1]);
        p[1] = make_ulonglong2(acc[i][2], acc[i][3]);
    }
}

// ---------------------------------------------------------------------------
// K2b: reduce the 4 partials -> g_bproj + exact row-min g_minb.
// ---------------------------------------------------------------------------
__global__ __launch_bounds__(256) void reduce_kernel() {
    const int row = blockIdx.x * 256 + threadIdx.x;
    const float4* p0 = (const float4*)(g_part + ((size_t)0 * M_TOT + row) * N_ST);
    const float4* p1 = (const float4*)(g_part + ((size_t)1 * M_TOT + row) * N_ST);
    const float4* p2 = (const float4*)(g_part + ((size_t)2 * M_TOT + row) * N_ST);
    const float4* p3 = (const float4*)(g_part + ((size_t)3 * M_TOT + row) * N_ST);
    float4* dst = (float4*)(g_bproj + (size_t)row * N_ST);

    float mn = 1e30f;
    #pragma unroll
    for (int q = 0; q < 16; q++) {
        float4 a = p0[q], b = p1[q], c = p2[q], d = p3[q];
        float4 s;
        s.x = (a.x + b.x) + (c.x + d.x);
        s.y = (a.y + b.y) + (c.y + d.y);
        s.z = (a.z + b.z) + (c.z + d.z);
        s.w = (a.w + b.w) + (c.w + d.w);
        mn = fminf(mn, fminf(fminf(s.x, s.y), fminf(s.z, s.w)));
        dst[q] = s;
    }
    g_minb[row] = mn;
}

// ---------------------------------------------------------------------------
// K3: fused scan+fix (unchanged, proven). Profiled this round (index 3).
// ---------------------------------------------------------------------------
__device__ void fix_one(const float* __restrict__ x, int row0, int t, int d) {
    int s = t - 1;
    while (s >= 0) {
        float xs = x[((size_t)(row0 + s) << 10) + d];
        if (xs * g_minb[row0 + s] >= 1.0f) break;
        s--;
    }
    float h[N_ST];
    const float hinit = (s >= 0) ? 1.0f : 0.0f;
    #pragma unroll
    for (int n = 0; n < N_ST; n++) h[n] = hinit;

    const float4* ar = (const float4*)(g_sgA + (size_t)d * N_ST);
    for (int u = s + 1; u <= t; u++) {
        const float xu = x[((size_t)(row0 + u) << 10) + d];
        const float4* bp = (const float4*)(g_bproj + ((size_t)(row0 + u) << 6));
        #pragma unroll
        for (int q = 0; q < 16; q++) {
            float4 av = ar[q];
            float4 bv = bp[q];
            h[4 * q + 0] = fminf(fmaf(bv.x, xu, h[4 * q + 0] * av.x), 1.0f);
            h[4 * q + 1] = fminf(fmaf(bv.y, xu, h[4 * q + 1] * av.y), 1.0f);
            h[4 * q + 2] = fminf(fmaf(bv.z, xu, h[4 * q + 2] * av.z), 1.0f);
            h[4 * q + 3] = fminf(fmaf(bv.w, xu, h[4 * q + 3] * av.w), 1.0f);
        }
    }

    const float4* cr = (const float4*)(g_sgC + (size_t)d * N_ST);
    float y0 = 0.f, y1 = 0.f, y2 = 0.f, y3 = 0.f;
    #pragma unroll
    for (int q = 0; q < 16; q++) {
        float4 cv = cr[q];
        y0 = fmaf(h[4 * q + 0], cv.x, y0);
        y1 = fmaf(h[4 * q + 1], cv.y, y1);
        y2 = fmaf(h[4 * q + 2], cv.z, y2);
        y3 = fmaf(h[4 * q + 3], cv.w, y3);
    }
    g_yraw[((size_t)(row0 + t) << 10) + d] = (y0 + y1) + (y2 + y3);
}

__global__ __launch_bounds__(256) void scanfix_kernel(const float* __restrict__ x) {
    const int w   = blockIdx.x * 256 + threadIdx.x;
    const int row = w >> 5;
    const float mb = g_minb[row];
    const float4* xp = (const float4*)(x + ((size_t)w << 5));

    unsigned m = 0u;
    #pragma unroll
    for (int j = 0; j < 8; j++) {
        float4 v = xp[j];
        if (v.x * mb < 1.0f) m |= 1u << (4 * j + 0);
        if (v.y * mb < 1.0f) m |= 1u << (4 * j + 1);
        if (v.z * mb < 1.0f) m |= 1u << (4 * j + 2);
        if (v.w * mb < 1.0f) m |= 1u << (4 * j + 3);
    }
    if (m == 0u) return;

    const int row0  = row & ~(S_LEN - 1);
    const int t     = row & (S_LEN - 1);
    const int dbase = (w & 31) * 32;
    while (m) {
        const int c = __ffs(m) - 1;
        m &= m - 1;
        fix_one(x, row0, t, dbase + c);
    }
}

// ---------------------------------------------------------------------------
// K4: TopologicalNorm + residual + clip (unchanged, proven)
// ---------------------------------------------------------------------------
__global__ __launch_bounds__(256) void ln_kernel(const float* __restrict__ x,
                                                 float* __restrict__ out) {
    const int row  = blockIdx.x * 8 + (threadIdx.x >> 5);
    const int lane = threadIdx.x & 31;

    const float mb = g_minb[row];
    const float* yrawr = g_yraw + ((size_t)row << 10);
    const float4* xr   = (const float4*)(x + ((size_t)row << 10));
    float4*       orow = (float4*)(out + ((size_t)row << 10));
    const float4* gr   = (const float4*)g_sgG;
    const float4* sr   = (const float4*)g_sumC;

    float4 v[8], xv[8];
    float sum = 0.0f;
    #pragma unroll
    for (int i = 0; i < 8; i++) {
        const int idx = lane + 32 * i;
        float4 x4 = xr[idx];
        float4 s4 = sr[idx];
        float4 y4;
        y4.x = (x4.x * mb >= 1.0f) ? s4.x : yrawr[4 * idx + 0];
        y4.y = (x4.y * mb >= 1.0f) ? s4.y : yrawr[4 * idx + 1];
        y4.z = (x4.z * mb >= 1.0f) ? s4.z : yrawr[4 * idx + 2];
        y4.w = (x4.w * mb >= 1.0f) ? s4.w : yrawr[4 * idx + 3];
        v[i] = y4;
        xv[i] = x4;
        sum += (y4.x + y4.y) + (y4.z + y4.w);
    }
    #pragma unroll
    for (int o = 16; o > 0; o >>= 1) sum += __shfl_xor_sync(0xffffffffu, sum, o);
    const float mean = sum * (1.0f / 1024.0f);

    float ss = 0.0f;
    #pragma unroll
    for (int i = 0; i < 8; i++) {
        float dx = v[i].x - mean, dy = v[i].y - mean;
        float dz = v[i].z - mean, dw = v[i].w - mean;
        ss += (dx * dx + dy * dy) + (dz * dz + dw * dw);
    }
    #pragma unroll
    for (int o = 16; o > 0; o >>= 1) ss += __shfl_xor_sync(0xffffffffu, ss, o);
    const float rstd = rsqrtf(ss * (1.0f / 1024.0f) + 1e-5f);

    #pragma unroll
    for (int i = 0; i < 8; i++) {
        float4 g4 = gr[lane + 32 * i];
        float4 o4;
        o4.x = fminf(fmaxf((v[i].x - mean) * rstd * g4.x + xv[i].x, 0.0f), 1.0f);
        o4.y = fminf(fmaxf((v[i].y - mean) * rstd * g4.y + xv[i].y, 0.0f), 1.0f);
        o4.z = fminf(fmaxf((v[i].z - mean) * rstd * g4.z + xv[i].z, 0.0f), 1.0f);
        o4.w = fminf(fmaxf((v[i].w - mean) * rstd * g4.w + xv[i].w, 0.0f), 1.0f);
        orow[lane + 32 * i] = o4;
    }
}

// ---------------------------------------------------------------------------
// noops removed (-7 us). ncu captures 0-based launch index 3 -> scanfix_kernel
// (the last never-profiled kernel).
// ---------------------------------------------------------------------------
extern "C" void kernel_launch(void* const* d_in, const int* in_sizes, int n_in,
                              void* d_out, int out_size) {
    const float* x     = (const float*)d_in[0];
    const float* A     = (const float*)d_in[1];
    const float* WB    = (const float*)d_in[2];
    const float* WC    = (const float*)d_in[3];
    const float* gamma = (const float*)d_in[4];
    float* out = (float*)d_out;

    precompute_kernel<<<256, 256>>>(A, WB, WC, gamma);     // 0
    bproj_gemm<<<(M_TOT / 128) * KSPLIT, 128>>>(x);        // 1
    reduce_kernel<<<M_TOT / 256, 256>>>();                 // 2
    scanfix_kernel<<<M_TOT * D_DIM / 32 / 256, 256>>>(x);  // 3  <- profiled
    ln_kernel<<<M_TOT / 8, 256>>>(x, out);                 // 4
}